// round 16
// baseline (speedup 1.0000x reference)
#include <cuda_runtime.h>
#include <cuda_pipeline.h>
#include <math.h>

#define LEVEL 16
#define TPB 128
#define MAXG 2048

// All counters MONOTONIC (never reset) -> deterministic under graph replay:
// per launch, g_t1 and g_t2 each advance by exactly NB+G (every CTA's last
// grab fails exactly once), g_arrive by exactly G.
__device__ double             g_partials[MAXG];
__device__ unsigned long long g_t1;       // phase-1 batch tickets
__device__ unsigned long long g_t2;       // phase-2 batch tickets
__device__ unsigned long long g_arrive;   // barrier arrivals

// One ST-BIF neuron step (matches reference: neg overrides pos).
__device__ __forceinline__ float bif_step(float& v, float& T, float xt, float v_th) {
    v += xt;
    float s = 0.0f;
    if (v - v_th >= 0.0f && T - 15.0f < 0.0f) s = 1.0f;
    if (v < 0.0f && T > 0.0f)                 s = -1.0f;
    v -= v_th * s;
    T += s;
    return s;
}

__device__ __forceinline__ void scan_batch(const float4* r, float4* __restrict__ out,
                                           int j, int M4, float v_th) {
    float vx = 0.5f * v_th, vy = vx, vz = vx, vw = vx;
    float Tx = 0.f, Ty = 0.f, Tz = 0.f, Tw = 0.f;
#pragma unroll
    for (int t = 0; t < LEVEL; t++) {
        float4 o;
        o.x = bif_step(vx, Tx, r[t].x, v_th) * v_th;
        o.y = bif_step(vy, Ty, r[t].y, v_th) * v_th;
        o.z = bif_step(vz, Tz, r[t].z, v_th) * v_th;
        o.w = bif_step(vw, Tw, r[t].w, v_th) * v_th;
        __stcs(&out[(size_t)t * M4 + j], o);
    }
}

// CTA-collective ticket grab: returns launch-local ticket index in [0, NB+G).
__device__ __forceinline__ int grab(unsigned long long* ctr, unsigned long long NBG,
                                    volatile unsigned long long* s_tick) {
    if (threadIdx.x == 0) *s_tick = atomicAdd(ctr, 1ULL);
    __syncthreads();
    int k = (int)(*s_tick % NBG);
    __syncthreads();          // everyone has read before the next overwrite
    return k;
}

// ---------------------------------------------------------------------------
// Single-wave persistent fused kernel, work-stealing both phases.
// Phase 2 is a cp.async double-issue pipeline: batch n+1's 16x16B per-thread
// async copies (global->smem, no registers) are in flight during batch n's
// compute+stores, so reads flow continuously through the mixed r/w phase.
// Each thread consumes ONLY its own copied smem bytes -> no syncthreads in
// the loop, single 32KB stage buffer is race-free.
// ---------------------------------------------------------------------------
__global__ void __launch_bounds__(TPB) fused_kernel(const float4* __restrict__ x,
                                                    float4* __restrict__ out, int M4) {
    const int G  = gridDim.x;
    const int NB = (M4 + TPB - 1) / TPB;              // batches (CTA-sized)
    const unsigned long long NBG = (unsigned long long)NB + (unsigned long long)G;
    const int tid = threadIdx.x;
    const int lane = tid & 31, wid = tid >> 5;

    __shared__ unsigned long long s_tick;
    __shared__ unsigned long long s_target;
    __shared__ float wsum[TPB / 32];
    __shared__ float s_vth;
    __shared__ float4 stage[LEVEL][TPB];              // 32 KB cp.async stage

    float4 r[LEVEL];

    // ---- Phase 1: work-stealing reduction, grab hidden under load burst ----
    float acc = 0.0f;
    int k = grab(&g_t1, NBG, &s_tick);
    while (k < NB) {
        int j = k * TPB + tid;
        bool v = (j < M4);
        if (v) {
#pragma unroll
            for (int t = 0; t < LEVEL; t++)
                r[t] = __ldcg(&x[(size_t)t * M4 + j]);
        }
        int kn = grab(&g_t1, NBG, &s_tick);           // overlaps load flight
        if (v) {
            float sx = 0.f, sy = 0.f, sz = 0.f, sw = 0.f;
#pragma unroll
            for (int t = 0; t < LEVEL; t++) {
                sx += r[t].x; sy += r[t].y; sz += r[t].z; sw += r[t].w;
            }
            acc += fabsf(sx) + fabsf(sy) + fabsf(sz) + fabsf(sw);
        }
        k = kn;
    }

    // ---- CTA reduce -> partial, arrive on barrier ----
#pragma unroll
    for (int o = 16; o > 0; o >>= 1)
        acc += __shfl_down_sync(0xFFFFFFFFu, acc, o);
    if (lane == 0) wsum[wid] = acc;
    __syncthreads();
    if (tid == 0) {
        float a = 0.f;
#pragma unroll
        for (int i = 0; i < TPB / 32; i++) a += wsum[i];
        g_partials[blockIdx.x] = (double)a;
        __threadfence();
        unsigned long long old = atomicAdd(&g_arrive, 1ULL);
        s_target = (old / (unsigned long long)G + 1ULL) * (unsigned long long)G;
    }
    __syncthreads();
    const unsigned long long target = s_target;

    // ---- Pre-grab first phase-2 batch, ISSUE its cp.asyncs before spin ----
    int k2 = grab(&g_t2, NBG, &s_tick);
    bool have = (k2 < NB);
    int j2 = (NB - 1 - k2) * TPB + tid;               // reverse j mapping
    bool val = have && (j2 < M4);
    if (val) {
#pragma unroll
        for (int t = 0; t < LEVEL; t++)
            __pipeline_memcpy_async(&stage[t][tid], &x[(size_t)t * M4 + j2], 16);
    }
    __pipeline_commit();

    // ---- Barrier spin + decentralized v_th (copies in flight) ----
    if (tid < 32) {
        if (lane == 0) {
            while (atomicAdd(&g_arrive, 0ULL) < target) __nanosleep(64);
        }
        __syncwarp();
        __threadfence();
        double d = 0.0;
        for (int i = lane; i < G; i += 32)
            d += g_partials[i];
#pragma unroll
        for (int o = 16; o > 0; o >>= 1)
            d += __shfl_down_sync(0xFFFFFFFFu, d, o);
        if (lane == 0) {
            double mean = d / (4.0 * (double)M4);
            s_vth = (float)(mean * 2.0 / sqrt(15.0));
        }
    }
    __syncthreads();
    const float v_th = s_vth;

    // ---- Phase 2: pipelined work-stealing scan ----
    while (have) {
        int kn = grab(&g_t2, NBG, &s_tick);           // overlaps copy flight

        __pipeline_wait_prior(0);                     // own batch-n bytes ready
        if (val) {
#pragma unroll
            for (int t = 0; t < LEVEL; t++)
                r[t] = stage[t][tid];                 // LDS.128, conflict-free
        }

        // Issue batch n+1's copies BEFORE consuming batch n (reads keep
        // flowing through the whole compute+store window).
        bool have_n = (kn < NB);
        int jn = (NB - 1 - kn) * TPB + tid;
        bool val_n = have_n && (jn < M4);
        if (val_n) {
#pragma unroll
            for (int t = 0; t < LEVEL; t++)
                __pipeline_memcpy_async(&stage[t][tid], &x[(size_t)t * M4 + jn], 16);
        }
        __pipeline_commit();

        if (val) scan_batch(r, out, j2, M4, v_th);    // compute + 16 stores

        have = have_n; val = val_n; j2 = jn;
    }
}

extern "C" void kernel_launch(void* const* d_in, const int* in_sizes, int n_in,
                              void* d_out, int out_size) {
    const float4* x = (const float4*)d_in[0];
    float4* out = (float4*)d_out;

    int n_total = in_sizes[0];         // 32*2048*1024
    int M4 = n_total / LEVEL / 4;      // 1,048,576 float4 columns

    // Single-wave grid: co-residency guaranteed -> spin-barrier is safe.
    int dev = 0;
    cudaGetDevice(&dev);
    int sms = 0;
    cudaDeviceGetAttribute(&sms, cudaDevAttrMultiProcessorCount, dev);
    int nb = 0;
    cudaOccupancyMaxActiveBlocksPerMultiprocessor(&nb, fused_kernel, TPB, 0);
    if (nb < 1) nb = 1;
    long long G = (long long)sms * nb;
    if (G > MAXG) G = MAXG;

    fused_kernel<<<(int)G, TPB>>>(x, out, M4);
}

// round 17
// speedup vs baseline: 1.0486x; 1.0486x over previous
#include <cuda_runtime.h>
#include <math.h>

#define LEVEL 16
#define TPB 128
#define MAXG 2048

// All counters MONOTONIC (never reset) -> deterministic under graph replay:
// per launch, g_t1 and g_t2 each advance by exactly NB+G (every CTA's last
// grab fails exactly once), g_arrive by exactly G.
__device__ double             g_partials[MAXG];
__device__ unsigned long long g_t1;       // phase-1 batch tickets
__device__ unsigned long long g_t2;       // phase-2 batch tickets
__device__ unsigned long long g_arrive;   // barrier arrivals

// One ST-BIF neuron step (matches reference: neg overrides pos).
__device__ __forceinline__ float bif_step(float& v, float& T, float xt, float v_th) {
    v += xt;
    float s = 0.0f;
    if (v - v_th >= 0.0f && T - 15.0f < 0.0f) s = 1.0f;
    if (v < 0.0f && T > 0.0f)                 s = -1.0f;
    v -= v_th * s;
    T += s;
    return s;
}

// CTA-collective ticket grab: returns launch-local ticket index in [0, NB+G).
__device__ __forceinline__ int grab(unsigned long long* ctr, unsigned long long NBG,
                                    volatile unsigned long long* s_tick) {
    if (threadIdx.x == 0) *s_tick = atomicAdd(ctr, 1ULL);
    __syncthreads();
    int k = (int)(*s_tick % NBG);
    __syncthreads();          // everyone has read before the next overwrite
    return k;
}

// ---------------------------------------------------------------------------
// Single-wave persistent fused kernel, work-stealing both phases (R13 base).
// Phase 2 interleaves NEXT-batch loads into the scan chain: step t consumes
// r[t], immediately overwrites r[t] with next batch's plane-t load, then
// stores step t's output. Reads and writes hit DRAM concurrently at plane
// granularity, with zero extra registers/smem.
// ---------------------------------------------------------------------------
__global__ void __launch_bounds__(TPB) fused_kernel(const float4* __restrict__ x,
                                                    float4* __restrict__ out, int M4) {
    const int G  = gridDim.x;
    const int NB = (M4 + TPB - 1) / TPB;              // batches (CTA-sized)
    const unsigned long long NBG = (unsigned long long)NB + (unsigned long long)G;
    const int tid = threadIdx.x;
    const int lane = tid & 31, wid = tid >> 5;

    __shared__ unsigned long long s_tick;
    __shared__ unsigned long long s_target;
    __shared__ float wsum[TPB / 32];
    __shared__ float s_vth;

    float4 r[LEVEL];

    // ---- Phase 1: work-stealing reduction, grab hidden under load burst ----
    float acc = 0.0f;
    int k = grab(&g_t1, NBG, &s_tick);
    while (k < NB) {
        int j = k * TPB + tid;
        bool v = (j < M4);
        if (v) {
#pragma unroll
            for (int t = 0; t < LEVEL; t++)
                r[t] = __ldcg(&x[(size_t)t * M4 + j]);
        }
        int kn = grab(&g_t1, NBG, &s_tick);           // overlaps load flight
        if (v) {
            float sx = 0.f, sy = 0.f, sz = 0.f, sw = 0.f;
#pragma unroll
            for (int t = 0; t < LEVEL; t++) {
                sx += r[t].x; sy += r[t].y; sz += r[t].z; sw += r[t].w;
            }
            acc += fabsf(sx) + fabsf(sy) + fabsf(sz) + fabsf(sw);
        }
        k = kn;
    }

    // ---- CTA reduce -> partial, arrive on barrier ----
#pragma unroll
    for (int o = 16; o > 0; o >>= 1)
        acc += __shfl_down_sync(0xFFFFFFFFu, acc, o);
    if (lane == 0) wsum[wid] = acc;
    __syncthreads();
    if (tid == 0) {
        float a = 0.f;
#pragma unroll
        for (int i = 0; i < TPB / 32; i++) a += wsum[i];
        g_partials[blockIdx.x] = (double)a;
        __threadfence();
        unsigned long long old = atomicAdd(&g_arrive, 1ULL);
        s_target = (old / (unsigned long long)G + 1ULL) * (unsigned long long)G;
    }
    __syncthreads();
    const unsigned long long target = s_target;

    // ---- Pre-grab first phase-2 batch, ISSUE its loads before the spin ----
    int k2 = grab(&g_t2, NBG, &s_tick);
    bool have = (k2 < NB);
    int j2 = (NB - 1 - k2) * TPB + tid;               // reverse j mapping
    bool val = have && (j2 < M4);
    if (val) {
#pragma unroll
        for (int t = 0; t < LEVEL; t++)
            r[t] = __ldcs(&x[(size_t)t * M4 + j2]);
    }

    // ---- Barrier spin + decentralized v_th (loads in flight) ----
    if (tid < 32) {
        if (lane == 0) {
            while (atomicAdd(&g_arrive, 0ULL) < target) __nanosleep(64);
        }
        __syncwarp();
        __threadfence();
        double d = 0.0;
        for (int i = lane; i < G; i += 32)
            d += g_partials[i];
#pragma unroll
        for (int o = 16; o > 0; o >>= 1)
            d += __shfl_down_sync(0xFFFFFFFFu, d, o);
        if (lane == 0) {
            double mean = d / (4.0 * (double)M4);
            s_vth = (float)(mean * 2.0 / sqrt(15.0));
        }
    }
    __syncthreads();
    const float v_th = s_vth;

    // ---- Phase 2: work-stealing scan with in-place load interleave ----
    while (have) {
        int kn = grab(&g_t2, NBG, &s_tick);           // overlaps current loads
        bool have_n = (kn < NB);
        int jn = (NB - 1 - kn) * TPB + tid;
        bool val_n = have_n && (jn < M4);

        if (val) {
            float vx = 0.5f * v_th, vy = vx, vz = vx, vw = vx;
            float Tx = 0.f, Ty = 0.f, Tz = 0.f, Tw = 0.f;
#pragma unroll
            for (int t = 0; t < LEVEL; t++) {
                float4 o;
                o.x = bif_step(vx, Tx, r[t].x, v_th) * v_th;
                o.y = bif_step(vy, Ty, r[t].y, v_th) * v_th;
                o.z = bif_step(vz, Tz, r[t].z, v_th) * v_th;
                o.w = bif_step(vw, Tw, r[t].w, v_th) * v_th;
                // r[t] consumed -> immediately refill with next batch's plane t
                if (val_n) r[t] = __ldcs(&x[(size_t)t * M4 + jn]);
                __stcs(&out[(size_t)t * M4 + j2], o);
            }
        } else if (val_n) {
#pragma unroll
            for (int t = 0; t < LEVEL; t++)
                r[t] = __ldcs(&x[(size_t)t * M4 + jn]);
        }

        have = have_n; val = val_n; j2 = jn;
    }
}

extern "C" void kernel_launch(void* const* d_in, const int* in_sizes, int n_in,
                              void* d_out, int out_size) {
    const float4* x = (const float4*)d_in[0];
    float4* out = (float4*)d_out;

    int n_total = in_sizes[0];         // 32*2048*1024
    int M4 = n_total / LEVEL / 4;      // 1,048,576 float4 columns

    // Single-wave grid: co-residency guaranteed -> spin-barrier is safe.
    int dev = 0;
    cudaGetDevice(&dev);
    int sms = 0;
    cudaDeviceGetAttribute(&sms, cudaDevAttrMultiProcessorCount, dev);
    int nb = 0;
    cudaOccupancyMaxActiveBlocksPerMultiprocessor(&nb, fused_kernel, TPB, 0);
    if (nb < 1) nb = 1;
    long long G = (long long)sms * nb;
    if (G > MAXG) G = MAXG;

    fused_kernel<<<(int)G, TPB>>>(x, out, M4);
}